// round 2
// baseline (speedup 1.0000x reference)
#include <cuda_runtime.h>
#include <mma.h>
#include <type_traits>
#include <cstdint>

using namespace nvcuda;

#define N_B   64
#define P_P   64
#define ENC_C 1536
#define T_T   32
#define V_V   10000
#define E_E   512
#define A_A   512
#define H_H   512
#define XDIM  2560   // ENC + E + H
#define GDIM  2048   // 4*H
#define PENC  98304  // P * ENC

// ---------------- device scratch (module globals: allocation-free) ----------
__device__ float g_attn_img[N_B * P_P * A_A];   // 8 MB
__device__ float g_emb[T_T * N_B * E_E];        // 4 MB
__device__ float g_hall[T_T * N_B * H_H];       // 4 MB
__device__ float g_Wcat[GDIM * XDIM];           // 20 MB [W_ih | W_hh]
__device__ float g_bcat[GDIM];
__device__ float g_xcat[N_B * XDIM];            // [ctx | emb | h]
__device__ float g_gates[N_B * GDIM];
__device__ float g_cstate[N_B * H_H];
__device__ float g_attn_h[N_B * A_A];

// ---------------- generic tf32 WMMA GEMM ------------------------------------
// C(M,N) = A(M,K) @ op(B) (+ bias), tile 64x64, 4 warps of 32x32.
// BT=true : B is (N,K) row-major (compute A@B^T)
// BT=false: B is (K,N) row-major
// MODE 0: plain store (+bias). MODE 1: atomicAdd (bias added by z==0 block).
// MODE 2: store with row remap m=(t*64+n) -> row n*T+t (fc epilogue), +bias.
template<bool BT, int MODE>
__global__ void __launch_bounds__(128) gemm_tf32(
    const float* __restrict__ A, int lda,
    const float* __restrict__ B, int ldb,
    const float* __restrict__ bias,
    float* __restrict__ C, int ldc,
    int M, int N, int K, int kChunk)
{
    constexpr int SP = 68;
    __shared__ float As[64 * SP];
    __shared__ float Bs[64 * SP];

    const int m0   = blockIdx.y * 64;
    const int n0   = blockIdx.x * 64;
    const int kBeg = blockIdx.z * kChunk;
    const int kEnd = min(K, kBeg + kChunk);
    const int tid  = threadIdx.x;
    const int warp = tid >> 5;
    const int wm   = warp >> 1;   // 0..1
    const int wn   = warp & 1;    // 0..1

    using BLayout = typename std::conditional<BT, wmma::col_major, wmma::row_major>::type;

    wmma::fragment<wmma::accumulator, 16, 16, 8, float> acc[2][2];
    #pragma unroll
    for (int i = 0; i < 2; i++)
        #pragma unroll
        for (int j = 0; j < 2; j++)
            wmma::fill_fragment(acc[i][j], 0.0f);

    for (int ko = kBeg; ko < kEnd; ko += 64) {
        // ---- load A tile 64x64 (row m, k contiguous) ----
        #pragma unroll
        for (int i = 0; i < 8; i++) {
            int idx = tid + i * 128;
            int m   = idx >> 4;
            int k4  = (idx & 15) << 2;
            float4 v = *(const float4*)(A + (size_t)(m0 + m) * lda + ko + k4);
            *(float4*)(As + m * SP + k4) = v;
        }
        // ---- load B tile ----
        if (BT) {
            // Bs layout [n][k]; wmma col_major reads element (k,n) at ptr[n*SP+k]
            #pragma unroll
            for (int i = 0; i < 8; i++) {
                int idx = tid + i * 128;
                int n   = idx >> 4;
                int k4  = (idx & 15) << 2;
                int gn  = n0 + n;
                float4 v;
                if (gn < N) v = *(const float4*)(B + (size_t)gn * ldb + ko + k4);
                else        v = make_float4(0.f, 0.f, 0.f, 0.f);
                *(float4*)(Bs + n * SP + k4) = v;
            }
        } else {
            // Bs layout [k][n]; wmma row_major
            #pragma unroll
            for (int i = 0; i < 8; i++) {
                int idx = tid + i * 128;
                int k   = idx >> 4;
                int n4  = (idx & 15) << 2;
                float4 v = *(const float4*)(B + (size_t)(ko + k) * ldb + n0 + n4);
                *(float4*)(Bs + k * SP + n4) = v;
            }
        }
        __syncthreads();

        #pragma unroll
        for (int kk = 0; kk < 64; kk += 8) {
            wmma::fragment<wmma::matrix_a, 16, 16, 8, wmma::precision::tf32, wmma::row_major> af[2];
            wmma::fragment<wmma::matrix_b, 16, 16, 8, wmma::precision::tf32, BLayout>         bf[2];
            #pragma unroll
            for (int i = 0; i < 2; i++) {
                wmma::load_matrix_sync(af[i], &As[(wm * 32 + i * 16) * SP + kk], SP);
                #pragma unroll
                for (int e = 0; e < af[i].num_elements; e++)
                    af[i].x[e] = wmma::__float_to_tf32(af[i].x[e]);
                const float* bp = BT ? &Bs[(wn * 32 + i * 16) * SP + kk]
                                     : &Bs[kk * SP + wn * 32 + i * 16];
                wmma::load_matrix_sync(bf[i], bp, SP);
                #pragma unroll
                for (int e = 0; e < bf[i].num_elements; e++)
                    bf[i].x[e] = wmma::__float_to_tf32(bf[i].x[e]);
            }
            #pragma unroll
            for (int i = 0; i < 2; i++)
                #pragma unroll
                for (int j = 0; j < 2; j++)
                    wmma::mma_sync(acc[i][j], af[i], bf[j], acc[i][j]);
        }
        __syncthreads();
    }

    // ---- epilogue through smem (handles N edge, bias, atomic, remap) ----
    #pragma unroll
    for (int i = 0; i < 2; i++)
        #pragma unroll
        for (int j = 0; j < 2; j++)
            wmma::store_matrix_sync(&As[(wm * 32 + i * 16) * SP + wn * 32 + j * 16],
                                    acc[i][j], SP, wmma::mem_row_major);
    __syncthreads();

    for (int idx = tid; idx < 4096; idx += 128) {
        int m = idx >> 6, n = idx & 63;
        int gm = m0 + m, gn = n0 + n;
        if (gn >= N) continue;
        float v = As[m * SP + n];
        if (MODE == 0) {
            C[(size_t)gm * ldc + gn] = v + (bias ? bias[gn] : 0.0f);
        } else if (MODE == 1) {
            if (blockIdx.z == 0 && bias) v += bias[gn];
            atomicAdd(&C[(size_t)gm * ldc + gn], v);
        } else {
            int row = (gm & 63) * T_T + (gm >> 6);   // n*T + t
            C[(size_t)row * ldc + gn] = v + bias[gn];
        }
    }
}

// ---------------- prologue: embedding gather + state zero -------------------
__global__ void prep_kernel(const float* __restrict__ embW,
                            const int*   __restrict__ captions)
{
    int b = blockIdx.x;           // 0..2047 -> (t, n)
    int t = b >> 6, n = b & 63;
    int e = threadIdx.x;          // 512
    int cap = captions[n * T_T + t];
    float v = embW[(size_t)cap * E_E + e];
    g_emb[((size_t)t * N_B + n) * E_E + e] = v;
    if (t == 0) {
        g_xcat[n * XDIM + ENC_C + e]        = v;     // emb slot, step 0
        g_xcat[n * XDIM + ENC_C + E_E + e]  = 0.0f;  // h slot (init gemm adds)
        g_cstate[n * H_H + e]               = 0.0f;  // c (init gemm adds)
    }
}

// ---------------- prologue: concat LSTM weights -----------------------------
__global__ void wcat_kernel(const float* __restrict__ Wih, const float* __restrict__ bih,
                            const float* __restrict__ Whh, const float* __restrict__ bhh)
{
    int idx = blockIdx.x * 1024 + threadIdx.x;
    if (idx < GDIM * XDIM) {
        int j = idx / XDIM, k = idx % XDIM;
        g_Wcat[idx] = (k < ENC_C + E_E) ? Wih[j * (ENC_C + E_E) + k]
                                        : Whh[j * H_H + (k - ENC_C - E_E)];
    }
    if (idx < GDIM) g_bcat[idx] = bih[idx] + bhh[idx];
}

// ---------------- per-step: attention scores + softmax + context ------------
// one block per batch row n; also zero-fills g_gates for the following gemm
__global__ void attn_ctx_kernel(const float* __restrict__ features,
                                const float* __restrict__ fullW,
                                const float* __restrict__ fullb)
{
    const int n    = blockIdx.x;
    const int tid  = threadIdx.x;     // 256
    const int lane = tid & 31;
    const int warp = tid >> 5;

    __shared__ float w[A_A];
    __shared__ float ah[A_A];
    __shared__ float sc[P_P];

    for (int j = tid; j < GDIM; j += 256) g_gates[n * GDIM + j] = 0.0f;
    for (int a = tid; a < A_A; a += 256) {
        w[a]  = fullW[a];
        ah[a] = g_attn_h[n * A_A + a];
    }
    __syncthreads();

    const float* aim = g_attn_img + (size_t)n * P_P * A_A;
    for (int p = warp; p < P_P; p += 8) {
        float s = 0.0f;
        const float* row = aim + p * A_A;
        for (int a = lane; a < A_A; a += 32) {
            float e = ah[a] + row[a];
            if (e > 0.0f) s += e * w[a];
        }
        #pragma unroll
        for (int o = 16; o > 0; o >>= 1) s += __shfl_xor_sync(0xffffffffu, s, o);
        if (lane == 0) sc[p] = s + fullb[0];
    }
    __syncthreads();

    if (warp == 0) {
        float v0 = sc[lane], v1 = sc[lane + 32];
        float mx = fmaxf(v0, v1);
        #pragma unroll
        for (int o = 16; o > 0; o >>= 1) mx = fmaxf(mx, __shfl_xor_sync(0xffffffffu, mx, o));
        float e0 = __expf(v0 - mx), e1 = __expf(v1 - mx);
        float sm = e0 + e1;
        #pragma unroll
        for (int o = 16; o > 0; o >>= 1) sm += __shfl_xor_sync(0xffffffffu, sm, o);
        float inv = 1.0f / sm;
        sc[lane]      = e0 * inv;
        sc[lane + 32] = e1 * inv;
    }
    __syncthreads();

    const float* fn  = features + (size_t)n * P_P * ENC_C;
    float*       ctx = g_xcat + n * XDIM;
    for (int c = tid; c < ENC_C; c += 256) {
        float acc = 0.0f;
        #pragma unroll 8
        for (int p = 0; p < P_P; p++) acc += sc[p] * fn[(size_t)p * ENC_C + c];
        ctx[c] = acc;
    }
}

// ---------------- per-step: LSTM pointwise + state forwarding ---------------
__global__ void lstm_point(int t)
{
    const int n = blockIdx.x, j = threadIdx.x;  // 64 x 512
    const float* g = g_gates + n * GDIM;
    float gi = g[j], gf = g[j + 512], gg = g[j + 1024], go = g[j + 1536];
    float c_old = g_cstate[n * H_H + j];
    float si = 1.0f / (1.0f + __expf(-gi));
    float sf = 1.0f / (1.0f + __expf(-gf));
    float so = 1.0f / (1.0f + __expf(-go));
    float cn = sf * c_old + si * tanhf(gg);
    float hn = so * tanhf(cn);
    g_cstate[n * H_H + j] = cn;
    g_hall[((size_t)t * N_B + n) * H_H + j] = hn;
    g_xcat[n * XDIM + ENC_C + E_E + j] = hn;                    // h slot
    if (t + 1 < T_T)
        g_xcat[n * XDIM + ENC_C + j] = g_emb[((size_t)(t + 1) * N_B + n) * E_E + j];
}

// ---------------- launch ----------------------------------------------------
extern "C" void kernel_launch(void* const* d_in, const int* in_sizes, int n_in,
                              void* d_out, int out_size)
{
    const float* features     = (const float*)d_in[0];
    const int*   captions     = (const int*)  d_in[1];
    const float* embd_W       = (const float*)d_in[2];
    const float* attn_token_W = (const float*)d_in[3];
    const float* attn_token_b = (const float*)d_in[4];
    const float* attn_feat_W  = (const float*)d_in[5];
    const float* attn_feat_b  = (const float*)d_in[6];
    const float* attn_full_W  = (const float*)d_in[7];
    const float* attn_full_b  = (const float*)d_in[8];
    const float* W_ih         = (const float*)d_in[9];
    const float* b_ih         = (const float*)d_in[10];
    const float* W_hh         = (const float*)d_in[11];
    const float* b_hh         = (const float*)d_in[12];
    const float* fc_W         = (const float*)d_in[13];
    const float* fc_b         = (const float*)d_in[14];
    const float* init_Wh      = (const float*)d_in[15];
    const float* init_Wc      = (const float*)d_in[16];
    float* out = (float*)d_out;

    float *p_attn_img, *p_Wcat, *p_bcat, *p_xcat, *p_gates, *p_c, *p_attn_h, *p_hall;
    cudaGetSymbolAddress((void**)&p_attn_img, g_attn_img);
    cudaGetSymbolAddress((void**)&p_Wcat,     g_Wcat);
    cudaGetSymbolAddress((void**)&p_bcat,     g_bcat);
    cudaGetSymbolAddress((void**)&p_xcat,     g_xcat);
    cudaGetSymbolAddress((void**)&p_gates,    g_gates);
    cudaGetSymbolAddress((void**)&p_c,        g_cstate);
    cudaGetSymbolAddress((void**)&p_attn_h,   g_attn_h);
    cudaGetSymbolAddress((void**)&p_hall,     g_hall);

    dim3 blk(128);

    // prologue
    prep_kernel<<<T_T * N_B, 512>>>(embd_W, captions);
    wcat_kernel<<<(GDIM * XDIM + 1023) / 1024, 1024>>>(W_ih, b_ih, W_hh, b_hh);

    // h0 = feat_flat @ init_Wh  (split-K=96, atomicAdd into x_cat h-slot)
    gemm_tf32<false, 1><<<dim3(8, 1, 96), blk>>>(
        features, PENC, init_Wh, H_H, nullptr,
        p_xcat + ENC_C + E_E, XDIM, N_B, H_H, PENC, 1024);
    // c0 = feat_flat @ init_Wc
    gemm_tf32<false, 1><<<dim3(8, 1, 96), blk>>>(
        features, PENC, init_Wc, H_H, nullptr,
        p_c, H_H, N_B, H_H, PENC, 1024);
    // attn_img = features @ attn_feat_W^T + b   (4096 x 512, K=1536)
    gemm_tf32<true, 0><<<dim3(8, 64, 1), blk>>>(
        features, ENC_C, attn_feat_W, ENC_C, attn_feat_b,
        p_attn_img, A_A, N_B * P_P, A_A, ENC_C, ENC_C);

    // sequential decode
    for (int t = 0; t < T_T; t++) {
        // attn_h = h @ attn_token_W^T + b
        gemm_tf32<true, 0><<<dim3(8, 1, 1), blk>>>(
            p_xcat + ENC_C + E_E, XDIM, attn_token_W, H_H, attn_token_b,
            p_attn_h, A_A, N_B, A_A, H_H, H_H);
        // attention scores + softmax + ctx (also zeroes gates)
        attn_ctx_kernel<<<N_B, 256>>>(features, attn_full_W, attn_full_b);
        // gates = x_cat @ Wcat^T + bcat  (split-K=4, atomicAdd)
        gemm_tf32<true, 1><<<dim3(32, 1, 4), blk>>>(
            p_xcat, XDIM, p_Wcat, XDIM, p_bcat,
            p_gates, GDIM, N_B, GDIM, XDIM, 640);
        // LSTM pointwise + forward h/emb into x_cat
        lstm_point<<<N_B, 512>>>(t);
    }

    // preds = h_all @ fc_W^T + fc_b, remapped to (N, T, V)
    gemm_tf32<true, 2><<<dim3((V_V + 63) / 64, 32, 1), blk>>>(
        p_hall, H_H, fc_W, H_H, fc_b,
        out, V_V, T_T * N_B, V_V, H_H, H_H);
}

// round 4
// speedup vs baseline: 1.3998x; 1.3998x over previous
#include <cuda_runtime.h>
#include <mma.h>
#include <type_traits>
#include <cstdint>

using namespace nvcuda;

#define N_B   64
#define P_P   64
#define ENC_C 1536
#define T_T   32
#define V_V   10000
#define E_E   512
#define A_A   512
#define H_H   512
#define XDIM  2560   // ENC + E + H
#define GDIM  2048   // 4*H
#define PENC  98304  // P * ENC
#define HOFF  (ENC_C + E_E)   // 2048, offset of h inside xcat
#define NBLK  128

// ---------------- device scratch (module globals: allocation-free) ----------
__device__ float g_attn_img[N_B * P_P * A_A];   // 8 MB
__device__ float g_emb[T_T * N_B * E_E];        // 4 MB
__device__ float g_hall[T_T * N_B * H_H];       // 4 MB
__device__ float g_Wcat[GDIM * XDIM];           // 20 MB [W_ih | W_hh]
__device__ float g_bcat[GDIM];
__device__ float g_xcat[N_B * XDIM];            // [ctx | emb | h]
__device__ float g_gpart[4 * N_B * GDIM];       // split-K partials (deterministic)
__device__ float g_cstate[N_B * H_H];
__device__ float g_attn_h[N_B * A_A];

// ---------------- grid-wide barrier (128 co-resident blocks) ----------------
__device__ unsigned g_cnt;
__device__ unsigned g_gen;

__device__ __forceinline__ void grid_sync() {
    __syncthreads();
    if (threadIdx.x == 0) {
        volatile unsigned* vgen = &g_gen;
        unsigned gen = *vgen;
        __threadfence();
        if (atomicAdd(&g_cnt, 1u) == NBLK - 1) {
            g_cnt = 0;
            __threadfence();
            *vgen = gen + 1;
        } else {
            while (*vgen == gen) { }
        }
    }
    __syncthreads();
}

// ---------------- big tiled tf32 GEMM: 64(M) x 128(N) tile, prefetch --------
// BT=true : B is (N,K) row-major (A @ B^T);  BT=false: B is (K,N) row-major
// MODE 0: C = v + bias. MODE 1 (init): atomicAdd, cols<512 -> C, else C2;
//         B2 supplies the second weight matrix for col tiles >= 512.
// MODE 2: fc remap row (gm&63)*T + (gm>>6), + bias.
template<bool BT, int MODE>
__global__ void __launch_bounds__(256, 2) gemm_k(
    const float* __restrict__ A, int lda,
    const float* __restrict__ B, const float* __restrict__ B2, int ldb,
    const float* __restrict__ bias,
    float* __restrict__ C, int ldc,
    float* __restrict__ C2, int ldc2,
    int N, int K, int kChunk)
{
    __shared__ float sh[64 * 132];           // 33.8 KB; aliased for stage
    float* As = sh;                          // [64][36]
    float* Bs = sh + 64 * 36;                // BT: [128][36]; !BT: [32][132]

    const int m0   = blockIdx.y * 64;
    const int n0   = blockIdx.x * 128;
    const int kBeg = blockIdx.z * kChunk;
    const int kEnd = min(K, kBeg + kChunk);
    const int tid  = threadIdx.x;
    const int warp = tid >> 5;

    const float* Bp = B;
    int nB0 = n0;
    if (MODE == 1 && n0 >= 512) { Bp = B2; nB0 = n0 - 512; }

    wmma::fragment<wmma::accumulator, 16, 16, 8, float> acc[4];
    #pragma unroll
    for (int i = 0; i < 4; i++) wmma::fill_fragment(acc[i], 0.0f);

    float4 ra[2], rb[4];
    // prologue prefetch
    {
        const int ko = kBeg;
        #pragma unroll
        for (int i = 0; i < 2; i++) {
            int idx = tid + i * 256, m = idx >> 3, k4 = (idx & 7) << 2;
            ra[i] = *(const float4*)(A + (size_t)(m0 + m) * lda + ko + k4);
        }
        #pragma unroll
        for (int i = 0; i < 4; i++) {
            int idx = tid + i * 256;
            if (BT) {
                int n = idx >> 3, k4 = (idx & 7) << 2, gn = n0 + n;
                rb[i] = (gn < N) ? *(const float4*)(Bp + (size_t)gn * ldb + ko + k4)
                                 : make_float4(0.f, 0.f, 0.f, 0.f);
            } else {
                int k = idx >> 5, n4 = (idx & 31) << 2;
                rb[i] = *(const float4*)(Bp + (size_t)(ko + k) * ldb + nB0 + n4);
            }
        }
    }

    for (int ko = kBeg; ko < kEnd; ko += 32) {
        #pragma unroll
        for (int i = 0; i < 2; i++) {
            int idx = tid + i * 256, m = idx >> 3, k4 = (idx & 7) << 2;
            *(float4*)(As + m * 36 + k4) = ra[i];
        }
        #pragma unroll
        for (int i = 0; i < 4; i++) {
            int idx = tid + i * 256;
            if (BT) {
                int n = idx >> 3, k4 = (idx & 7) << 2;
                *(float4*)(Bs + n * 36 + k4) = rb[i];
            } else {
                int k = idx >> 5, n4 = (idx & 31) << 2;
                *(float4*)(Bs + k * 132 + n4) = rb[i];
            }
        }
        __syncthreads();

        const int kn = ko + 32;
        if (kn < kEnd) {
            #pragma unroll
            for (int i = 0; i < 2; i++) {
                int idx = tid + i * 256, m = idx >> 3, k4 = (idx & 7) << 2;
                ra[i] = *(const float4*)(A + (size_t)(m0 + m) * lda + kn + k4);
            }
            #pragma unroll
            for (int i = 0; i < 4; i++) {
                int idx = tid + i * 256;
                if (BT) {
                    int n = idx >> 3, k4 = (idx & 7) << 2, gn = n0 + n;
                    rb[i] = (gn < N) ? *(const float4*)(Bp + (size_t)gn * ldb + kn + k4)
                                     : make_float4(0.f, 0.f, 0.f, 0.f);
                } else {
                    int k = idx >> 5, n4 = (idx & 31) << 2;
                    rb[i] = *(const float4*)(Bp + (size_t)(kn + k) * ldb + nB0 + n4);
                }
            }
        }

        #pragma unroll
        for (int kk = 0; kk < 32; kk += 8) {
            wmma::fragment<wmma::matrix_b, 16, 16, 8, wmma::precision::tf32,
                typename std::conditional<BT, wmma::col_major, wmma::row_major>::type> bf;
            const float* bp = BT ? (Bs + (warp * 16) * 36 + kk)
                                 : (Bs + kk * 132 + warp * 16);
            wmma::load_matrix_sync(bf, bp, BT ? 36 : 132);
            #pragma unroll
            for (int e = 0; e < bf.num_elements; e++) bf.x[e] = wmma::__float_to_tf32(bf.x[e]);
            #pragma unroll
            for (int i = 0; i < 4; i++) {
                wmma::fragment<wmma::matrix_a, 16, 16, 8, wmma::precision::tf32, wmma::row_major> af;
                wmma::load_matrix_sync(af, As + (i * 16) * 36 + kk, 36);
                #pragma unroll
                for (int e = 0; e < af.num_elements; e++) af.x[e] = wmma::__float_to_tf32(af.x[e]);
                wmma::mma_sync(acc[i], af, bf, acc[i]);
            }
        }
        __syncthreads();
    }

    // epilogue: stage 64x128 into sh, then linear writes
    #pragma unroll
    for (int i = 0; i < 4; i++)
        wmma::store_matrix_sync(sh + (i * 16) * 132 + warp * 16, acc[i], 132, wmma::mem_row_major);
    __syncthreads();

    for (int idx = tid; idx < 64 * 128; idx += 256) {
        int m = idx >> 7, n = idx & 127;
        int gm = m0 + m, gn = n0 + n;
        if (gn >= N) continue;
        float v = sh[m * 132 + n];
        if (MODE == 0) {
            C[(size_t)gm * ldc + gn] = v + (bias ? bias[gn] : 0.0f);
        } else if (MODE == 1) {
            if (gn < 512) atomicAdd(&C[(size_t)gm * ldc + gn], v);
            else          atomicAdd(&C2[(size_t)gm * ldc2 + gn - 512], v);
        } else {
            int row = (gm & 63) * T_T + (gm >> 6);
            C[(size_t)row * ldc + gn] = v + bias[gn];
        }
    }
}

// ---------------- prologue: embedding gather + state zero -------------------
__global__ void prep_kernel(const float* __restrict__ embW,
                            const int*   __restrict__ captions)
{
    int b = blockIdx.x;           // (t, n)
    int t = b >> 6, n = b & 63;
    int e = threadIdx.x;          // 512
    int cap = captions[n * T_T + t];
    float v = embW[(size_t)cap * E_E + e];
    g_emb[((size_t)t * N_B + n) * E_E + e] = v;
    if (t == 0) {
        g_xcat[n * XDIM + ENC_C + e]       = v;     // emb slot, step 0
        g_xcat[n * XDIM + HOFF + e]        = 0.0f;  // h slot (init gemm adds)
        g_cstate[n * H_H + e]              = 0.0f;  // c (init gemm adds)
    }
}

// ---------------- prologue: concat LSTM weights -----------------------------
__global__ void wcat_kernel(const float* __restrict__ Wih, const float* __restrict__ bih,
                            const float* __restrict__ Whh, const float* __restrict__ bhh)
{
    int idx = blockIdx.x * 1024 + threadIdx.x;
    if (idx < GDIM * XDIM) {
        int j = idx / XDIM, k = idx % XDIM;
        g_Wcat[idx] = (k < HOFF) ? Wih[j * HOFF + k]
                                 : Whh[j * H_H + (k - HOFF)];
    }
    if (idx < GDIM) g_bcat[idx] = bih[idx] + bhh[idx];
}

// ---------------- persistent decode loop (all 32 steps, 4 phases/step) ------
__global__ void __launch_bounds__(256) decode_loop(
    const float* __restrict__ features,
    const float* __restrict__ tokW, const float* __restrict__ tokb,
    const float* __restrict__ fullW, const float* __restrict__ fullb)
{
    constexpr int SP = 68;
    __shared__ float As[64 * SP];
    __shared__ float Bs[64 * SP];
    __shared__ float s_w[A_A];
    __shared__ float s_ah[A_A];
    __shared__ float s_sc[P_P];

    const int b    = blockIdx.x;
    const int tid  = threadIdx.x;
    const int warp = tid >> 5;
    const int lane = tid & 31;

    // persistent cell state: this thread permanently owns element (en, ej)
    const int eidx = b * 256 + tid;
    const int en = eidx >> 9, ej = eidx & 511;
    float creg = g_cstate[en * H_H + ej];

    for (int t = 0; t < T_T; t++) {
        // ===== P1: attn_h = h @ tokW^T + tokb (blocks 0..15, 64x32 tiles) ===
        if (b < 16) {
            const int n0  = b * 32;
            const int m16 = (warp >> 1) * 16;
            const int n16 = (warp & 1) * 16;
            wmma::fragment<wmma::accumulator, 16, 16, 8, float> acc;
            wmma::fill_fragment(acc, 0.0f);
            for (int ko = 0; ko < H_H; ko += 64) {
                #pragma unroll
                for (int i = 0; i < 4; i++) {
                    int idx = tid + i * 256, m = idx >> 4, k4 = (idx & 15) << 2;
                    float4 v = __ldcg((const float4*)(g_xcat + (size_t)m * XDIM + HOFF + ko + k4));
                    *(float4*)(As + m * SP + k4) = v;
                }
                #pragma unroll
                for (int i = 0; i < 2; i++) {
                    int idx = tid + i * 256, n = idx >> 4, k4 = (idx & 15) << 2;
                    float4 v = *(const float4*)(tokW + (size_t)(n0 + n) * H_H + ko + k4);
                    *(float4*)(Bs + n * SP + k4) = v;
                }
                __syncthreads();
                #pragma unroll
                for (int kk = 0; kk < 64; kk += 8) {
                    wmma::fragment<wmma::matrix_a, 16, 16, 8, wmma::precision::tf32, wmma::row_major> af;
                    wmma::fragment<wmma::matrix_b, 16, 16, 8, wmma::precision::tf32, wmma::col_major> bf;
                    wmma::load_matrix_sync(af, As + m16 * SP + kk, SP);
                    #pragma unroll
                    for (int e = 0; e < af.num_elements; e++) af.x[e] = wmma::__float_to_tf32(af.x[e]);
                    wmma::load_matrix_sync(bf, Bs + n16 * SP + kk, SP);
                    #pragma unroll
                    for (int e = 0; e < bf.num_elements; e++) bf.x[e] = wmma::__float_to_tf32(bf.x[e]);
                    wmma::mma_sync(acc, af, bf, acc);
                }
                __syncthreads();
            }
            wmma::store_matrix_sync(As + m16 * SP + n16, acc, SP, wmma::mem_row_major);
            __syncthreads();
            for (int idx = tid; idx < 64 * 32; idx += 256) {
                int m = idx >> 5, n = idx & 31;
                g_attn_h[m * A_A + n0 + n] = As[m * SP + n] + tokb[n0 + n];
            }
        }
        grid_sync();

        // ===== P2: attention scores + softmax + ctx (pair of blocks per n) ==
        {
            const int n = b >> 1, half = b & 1;
            for (int a = tid; a < A_A; a += 256) {
                s_w[a]  = fullW[a];
                s_ah[a] = __ldcg(g_attn_h + n * A_A + a);
            }
            __syncthreads();

            const float* aim = g_attn_img + (size_t)n * P_P * A_A;
            for (int p = warp; p < P_P; p += 8) {
                float s = 0.0f;
                const float* row = aim + p * A_A;
                #pragma unroll 4
                for (int a = lane; a < A_A; a += 32) {
                    float e = s_ah[a] + row[a];
                    if (e > 0.0f) s += e * s_w[a];
                }
                #pragma unroll
                for (int o = 16; o > 0; o >>= 1) s += __shfl_xor_sync(0xffffffffu, s, o);
                if (lane == 0) s_sc[p] = s + fullb[0];
            }
            __syncthreads();

            if (warp == 0) {
                float v0 = s_sc[lane], v1 = s_sc[lane + 32];
                float mx = fmaxf(v0, v1);
                #pragma unroll
                for (int o = 16; o > 0; o >>= 1) mx = fmaxf(mx, __shfl_xor_sync(0xffffffffu, mx, o));
                float e0 = __expf(v0 - mx), e1 = __expf(v1 - mx);
                float sm = e0 + e1;
                #pragma unroll
                for (int o = 16; o > 0; o >>= 1) sm += __shfl_xor_sync(0xffffffffu, sm, o);
                float inv = 1.0f / sm;
                s_sc[lane]      = e0 * inv;
                s_sc[lane + 32] = e1 * inv;
            }
            __syncthreads();

            const float* fn  = features + (size_t)n * P_P * ENC_C;
            float*       ctx = g_xcat + n * XDIM;
            for (int c = half * 768 + tid; c < half * 768 + 768; c += 256) {
                float a0 = 0.0f;
                #pragma unroll 8
                for (int p = 0; p < P_P; p++) a0 += s_sc[p] * fn[(size_t)p * ENC_C + c];
                ctx[c] = a0;
            }
            __syncthreads();
        }
        grid_sync();

        // ===== P3: gates split-K GEMM -> deterministic partials =============
        {
            const int nt = b >> 2, kz = b & 3;
            const int n0 = nt * 64;
            const int kb = kz * 640;
            const int m16 = (warp >> 1) * 16;
            const int nb2 = (warp & 1) * 32;
            wmma::fragment<wmma::accumulator, 16, 16, 8, float> acc[2];
            wmma::fill_fragment(acc[0], 0.0f);
            wmma::fill_fragment(acc[1], 0.0f);
            for (int ko = kb; ko < kb + 640; ko += 64) {
                #pragma unroll
                for (int i = 0; i < 4; i++) {
                    int idx = tid + i * 256, m = idx >> 4, k4 = (idx & 15) << 2;
                    float4 v = __ldcg((const float4*)(g_xcat + (size_t)m * XDIM + ko + k4));
                    *(float4*)(As + m * SP + k4) = v;
                }
                #pragma unroll
                for (int i = 0; i < 4; i++) {
                    int idx = tid + i * 256, n = idx >> 4, k4 = (idx & 15) << 2;
                    float4 v = *(const float4*)(g_Wcat + (size_t)(n0 + n) * XDIM + ko + k4);
                    *(float4*)(Bs + n * SP + k4) = v;
                }
                __syncthreads();
                #pragma unroll
                for (int kk = 0; kk < 64; kk += 8) {
                    wmma::fragment<wmma::matrix_a, 16, 16, 8, wmma::precision::tf32, wmma::row_major> af;
                    wmma::load_matrix_sync(af, As + m16 * SP + kk, SP);
                    #pragma unroll
                    for (int e = 0; e < af.num_elements; e++) af.x[e] = wmma::__float_to_tf32(af.x[e]);
                    #pragma unroll
                    for (int j = 0; j < 2; j++) {
                        wmma::fragment<wmma::matrix_b, 16, 16, 8, wmma::precision::tf32, wmma::col_major> bf;
                        wmma::load_matrix_sync(bf, Bs + (nb2 + j * 16) * SP + kk, SP);
                        #pragma unroll
                        for (int e = 0; e < bf.num_elements; e++) bf.x[e] = wmma::__float_to_tf32(bf.x[e]);
                        wmma::mma_sync(acc[j], af, bf, acc[j]);
                    }
                }
                __syncthreads();
            }
            wmma::store_matrix_sync(As + m16 * SP + nb2,      acc[0], SP, wmma::mem_row_major);
            wmma::store_matrix_sync(As + m16 * SP + nb2 + 16, acc[1], SP, wmma::mem_row_major);
            __syncthreads();
            float* gp = g_gpart + (size_t)kz * (N_B * GDIM);
            for (int idx = tid; idx < 4096; idx += 256) {
                int m = idx >> 6, n = idx & 63;
                gp[m * GDIM + n0 + n] = As[m * SP + n];
            }
        }
        grid_sync();

        // ===== P4: LSTM pointwise (one element per thread, c in register) ===
        {
            float gi = g_bcat[ej];
            float gf = g_bcat[512 + ej];
            float gg = g_bcat[1024 + ej];
            float go = g_bcat[1536 + ej];
            #pragma unroll
            for (int kz = 0; kz < 4; kz++) {
                const float* g = g_gpart + (size_t)kz * (N_B * GDIM) + en * GDIM;
                gi += __ldcg(g + ej);
                gf += __ldcg(g + 512 + ej);
                gg += __ldcg(g + 1024 + ej);
                go += __ldcg(g + 1536 + ej);
            }
            float si = 1.0f / (1.0f + __expf(-gi));
            float sf = 1.0f / (1.0f + __expf(-gf));
            float so = 1.0f / (1.0f + __expf(-go));
            float cn = sf * creg + si * tanhf(gg);
            float hn = so * tanhf(cn);
            creg = cn;
            g_hall[((size_t)t * N_B + en) * H_H + ej] = hn;
            g_xcat[en * XDIM + HOFF + ej] = hn;
            if (t + 1 < T_T)
                g_xcat[en * XDIM + ENC_C + ej] = g_emb[((size_t)(t + 1) * N_B + en) * E_E + ej];
        }
        grid_sync();
    }
}

// ---------------- launch ----------------------------------------------------
extern "C" void kernel_launch(void* const* d_in, const int* in_sizes, int n_in,
                              void* d_out, int out_size)
{
    const float* features     = (const float*)d_in[0];
    const int*   captions     = (const int*)  d_in[1];
    const float* embd_W       = (const float*)d_in[2];
    const float* attn_token_W = (const float*)d_in[3];
    const float* attn_token_b = (const float*)d_in[4];
    const float* attn_feat_W  = (const float*)d_in[5];
    const float* attn_feat_b  = (const float*)d_in[6];
    const float* attn_full_W  = (const float*)d_in[7];
    const float* attn_full_b  = (const float*)d_in[8];
    const float* W_ih         = (const float*)d_in[9];
    const float* b_ih         = (const float*)d_in[10];
    const float* W_hh         = (const float*)d_in[11];
    const float* b_hh         = (const float*)d_in[12];
    const float* fc_W         = (const float*)d_in[13];
    const float* fc_b         = (const float*)d_in[14];
    const float* init_Wh      = (const float*)d_in[15];
    const float* init_Wc      = (const float*)d_in[16];
    float* out = (float*)d_out;

    float *p_attn_img, *p_xcat, *p_c, *p_hall;
    cudaGetSymbolAddress((void**)&p_attn_img, g_attn_img);
    cudaGetSymbolAddress((void**)&p_xcat,     g_xcat);
    cudaGetSymbolAddress((void**)&p_c,        g_cstate);
    cudaGetSymbolAddress((void**)&p_hall,     g_hall);

    // prologue
    prep_kernel<<<T_T * N_B, 512>>>(embd_W, captions);
    wcat_kernel<<<(GDIM * XDIM + 1023) / 1024, 1024>>>(W_ih, b_ih, W_hh, b_hh);

    // [h0 | c0] = feat_flat @ [Wh | Wc]  (merged, split-K=96, atomic)
    gemm_k<false, 1><<<dim3(8, 1, 96), 256>>>(
        features, PENC, init_Wh, init_Wc, H_H, nullptr,
        p_xcat + HOFF, XDIM, p_c, H_H, 1024, PENC, 1024);

    // attn_img = features @ attn_feat_W^T + b
    gemm_k<true, 0><<<dim3(4, 64, 1), 256>>>(
        features, ENC_C, attn_feat_W, nullptr, ENC_C, attn_feat_b,
        p_attn_img, A_A, nullptr, 0, A_A, ENC_C, ENC_C);

    // full 32-step decode in one persistent kernel
    decode_loop<<<NBLK, 256>>>(features, attn_token_W, attn_token_b,
                               attn_full_W, attn_full_b);

    // preds = h_all @ fc_W^T + fc_b, remapped to (N, T, V)
    gemm_k<true, 2><<<dim3((V_V + 127) / 128, 32, 1), 256>>>(
        p_hall, H_H, fc_W, nullptr, H_H, fc_b,
        out, V_V, nullptr, 0, V_V, H_H, H_H);
}

// round 5
// speedup vs baseline: 1.4182x; 1.0131x over previous
#include <cuda_runtime.h>
#include <mma.h>
#include <type_traits>
#include <cstdint>

using namespace nvcuda;

#define N_B   64
#define P_P   64
#define ENC_C 1536
#define T_T   32
#define V_V   10000
#define E_E   512
#define A_A   512
#define H_H   512
#define XDIM  2560   // ENC + E + H
#define GDIM  2048   // 4*H
#define PENC  98304  // P * ENC
#define HOFF  (ENC_C + E_E)   // 2048, offset of h inside xcat
#define NBLK  128

// ---------------- device scratch (module globals: allocation-free) ----------
__device__ float g_attn_img[N_B * P_P * A_A];   // 8 MB
__device__ float g_emb[T_T * N_B * E_E];        // 4 MB
__device__ float g_hall[T_T * N_B * H_H];       // 4 MB
__device__ float g_Wcat[GDIM * XDIM];           // 20 MB [W_ih | W_hh], tf32-rounded
__device__ float g_bcat[GDIM];
__device__ float g_xcat[N_B * XDIM];            // [ctx | emb | h]
__device__ float g_gpart[4 * N_B * GDIM];       // split-K partials (deterministic)
__device__ float g_cstate[N_B * H_H];
__device__ float g_attn_h[N_B * A_A];

// ---------------- grid-wide barrier (128 co-resident blocks) ----------------
__device__ unsigned g_cnt;
__device__ unsigned g_gen;

__device__ __forceinline__ void grid_sync() {
    __syncthreads();
    if (threadIdx.x == 0) {
        volatile unsigned* vgen = &g_gen;
        unsigned gen = *vgen;
        __threadfence();
        if (atomicAdd(&g_cnt, 1u) == NBLK - 1) {
            g_cnt = 0;
            __threadfence();
            *vgen = gen + 1;
        } else {
            while (*vgen == gen) { __nanosleep(64); }
        }
    }
    __syncthreads();
}

__device__ __forceinline__ float tf32r(float x) { return wmma::__float_to_tf32(x); }

// ---------------- 128x128-tile tf32 GEMM (A @ B^T + bias) -------------------
// A (M,K) row-major, B (N,K) row-major. tf32 rounding done at smem store.
// MODE 0: C[gm*ldc+gn] = v + bias. MODE 2: fc remap row (gm&63)*T+(gm>>6).
template<int MODE>
__global__ void __launch_bounds__(256, 2) gemm_big(
    const float* __restrict__ A, int lda,
    const float* __restrict__ B, int ldb,
    const float* __restrict__ bias,
    float* __restrict__ C, int ldc,
    int N, int K)
{
    __shared__ float sh[2 * 128 * 36];   // 36.9 KB; reused for epilogue staging
    float* As = sh;
    float* Bs = sh + 128 * 36;

    const int m0   = blockIdx.y * 128;
    const int n0   = blockIdx.x * 128;
    const int tid  = threadIdx.x;
    const int warp = tid >> 5;
    const int wm   = (warp & 3) << 5;    // 0,32,64,96
    const int wn   = (warp >> 2) << 6;   // 0,64

    wmma::fragment<wmma::accumulator, 16, 16, 8, float> acc[2][4];
    #pragma unroll
    for (int i = 0; i < 2; i++)
        #pragma unroll
        for (int j = 0; j < 4; j++) wmma::fill_fragment(acc[i][j], 0.0f);

    float4 ra[4], rb[4];

    // prologue prefetch
    #pragma unroll
    for (int i = 0; i < 4; i++) {
        int idx = tid + i * 256, m = idx >> 3, k4 = (idx & 7) << 2;
        ra[i] = *(const float4*)(A + (size_t)(m0 + m) * lda + k4);
        int gn = n0 + m;
        rb[i] = (gn < N) ? *(const float4*)(B + (size_t)gn * ldb + k4)
                         : make_float4(0.f, 0.f, 0.f, 0.f);
    }

    for (int ko = 0; ko < K; ko += 32) {
        #pragma unroll
        for (int i = 0; i < 4; i++) {
            int idx = tid + i * 256, m = idx >> 3, k4 = (idx & 7) << 2;
            float* pa = As + m * 36 + k4;
            pa[0] = tf32r(ra[i].x); pa[1] = tf32r(ra[i].y);
            pa[2] = tf32r(ra[i].z); pa[3] = tf32r(ra[i].w);
            float* pb = Bs + m * 36 + k4;
            pb[0] = tf32r(rb[i].x); pb[1] = tf32r(rb[i].y);
            pb[2] = tf32r(rb[i].z); pb[3] = tf32r(rb[i].w);
        }
        __syncthreads();

        const int kn = ko + 32;
        if (kn < K) {
            #pragma unroll
            for (int i = 0; i < 4; i++) {
                int idx = tid + i * 256, m = idx >> 3, k4 = (idx & 7) << 2;
                ra[i] = *(const float4*)(A + (size_t)(m0 + m) * lda + kn + k4);
                int gn = n0 + m;
                rb[i] = (gn < N) ? *(const float4*)(B + (size_t)gn * ldb + kn + k4)
                                 : make_float4(0.f, 0.f, 0.f, 0.f);
            }
        }

        #pragma unroll
        for (int kk = 0; kk < 32; kk += 8) {
            wmma::fragment<wmma::matrix_a, 16, 16, 8, wmma::precision::tf32, wmma::row_major> af[2];
            wmma::fragment<wmma::matrix_b, 16, 16, 8, wmma::precision::tf32, wmma::col_major> bf[4];
            #pragma unroll
            for (int i = 0; i < 2; i++)
                wmma::load_matrix_sync(af[i], As + (wm + i * 16) * 36 + kk, 36);
            #pragma unroll
            for (int j = 0; j < 4; j++)
                wmma::load_matrix_sync(bf[j], Bs + (wn + j * 16) * 36 + kk, 36);
            #pragma unroll
            for (int i = 0; i < 2; i++)
                #pragma unroll
                for (int j = 0; j < 4; j++)
                    wmma::mma_sync(acc[i][j], af[i], bf[j], acc[i][j]);
        }
        __syncthreads();
    }

    // epilogue: two N-half waves staged through smem [128][68]
    #pragma unroll
    for (int wave = 0; wave < 2; wave++) {
        if ((warp >> 2) == wave) {
            #pragma unroll
            for (int i = 0; i < 2; i++)
                #pragma unroll
                for (int j = 0; j < 4; j++)
                    wmma::store_matrix_sync(sh + (wm + i * 16) * 68 + j * 16,
                                            acc[i][j], 68, wmma::mem_row_major);
        }
        __syncthreads();
        for (int idx = tid; idx < 128 * 64; idx += 256) {
            int m = idx >> 6, nn = idx & 63;
            int gm = m0 + m, gn = n0 + wave * 64 + nn;
            if (gn >= N) continue;
            float v = sh[m * 68 + nn] + bias[gn];
            if (MODE == 0) {
                C[(size_t)gm * ldc + gn] = v;
            } else {
                int row = (gm & 63) * T_T + (gm >> 6);
                C[(size_t)row * ldc + gn] = v;
            }
        }
        __syncthreads();
    }
}

// ---------------- init GEMM: 64(M) x 128(N) tile, split-K atomic ------------
// B is (K,N) row-major; cols<512 -> C (Wh), else C2 (Wc via B2).
__global__ void __launch_bounds__(256, 2) gemm_init(
    const float* __restrict__ A, int lda,
    const float* __restrict__ B, const float* __restrict__ B2, int ldb,
    float* __restrict__ C, int ldc,
    float* __restrict__ C2, int ldc2,
    int K, int kChunk)
{
    __shared__ float sh[64 * 132];
    float* As = sh;                          // [64][36]
    float* Bs = sh + 64 * 36;                // [32][132]

    const int n0   = blockIdx.x * 128;
    const int kBeg = blockIdx.z * kChunk;
    const int kEnd = min(K, kBeg + kChunk);
    const int tid  = threadIdx.x;
    const int warp = tid >> 5;

    const float* Bp = B;
    int nB0 = n0;
    if (n0 >= 512) { Bp = B2; nB0 = n0 - 512; }

    wmma::fragment<wmma::accumulator, 16, 16, 8, float> acc[4];
    #pragma unroll
    for (int i = 0; i < 4; i++) wmma::fill_fragment(acc[i], 0.0f);

    float4 ra[2], rb[4];
    {
        const int ko = kBeg;
        #pragma unroll
        for (int i = 0; i < 2; i++) {
            int idx = tid + i * 256, m = idx >> 3, k4 = (idx & 7) << 2;
            ra[i] = *(const float4*)(A + (size_t)m * lda + ko + k4);
        }
        #pragma unroll
        for (int i = 0; i < 4; i++) {
            int idx = tid + i * 256, k = idx >> 5, n4 = (idx & 31) << 2;
            rb[i] = *(const float4*)(Bp + (size_t)(ko + k) * ldb + nB0 + n4);
        }
    }

    for (int ko = kBeg; ko < kEnd; ko += 32) {
        #pragma unroll
        for (int i = 0; i < 2; i++) {
            int idx = tid + i * 256, m = idx >> 3, k4 = (idx & 7) << 2;
            float* pa = As + m * 36 + k4;
            pa[0] = tf32r(ra[i].x); pa[1] = tf32r(ra[i].y);
            pa[2] = tf32r(ra[i].z); pa[3] = tf32r(ra[i].w);
        }
        #pragma unroll
        for (int i = 0; i < 4; i++) {
            int idx = tid + i * 256, k = idx >> 5, n4 = (idx & 31) << 2;
            float* pb = Bs + k * 132 + n4;
            pb[0] = tf32r(rb[i].x); pb[1] = tf32r(rb[i].y);
            pb[2] = tf32r(rb[i].z); pb[3] = tf32r(rb[i].w);
        }
        __syncthreads();

        const int kn = ko + 32;
        if (kn < kEnd) {
            #pragma unroll
            for (int i = 0; i < 2; i++) {
                int idx = tid + i * 256, m = idx >> 3, k4 = (idx & 7) << 2;
                ra[i] = *(const float4*)(A + (size_t)m * lda + kn + k4);
            }
            #pragma unroll
            for (int i = 0; i < 4; i++) {
                int idx = tid + i * 256, k = idx >> 5, n4 = (idx & 31) << 2;
                rb[i] = *(const float4*)(Bp + (size_t)(kn + k) * ldb + nB0 + n4);
            }
        }

        #pragma unroll
        for (int kk = 0; kk < 32; kk += 8) {
            wmma::fragment<wmma::matrix_b, 16, 16, 8, wmma::precision::tf32, wmma::row_major> bf;
            wmma::load_matrix_sync(bf, Bs + kk * 132 + warp * 16, 132);
            #pragma unroll
            for (int i = 0; i < 4; i++) {
                wmma::fragment<wmma::matrix_a, 16, 16, 8, wmma::precision::tf32, wmma::row_major> af;
                wmma::load_matrix_sync(af, As + (i * 16) * 36 + kk, 36);
                wmma::mma_sync(acc[i], af, bf, acc[i]);
            }
        }
        __syncthreads();
    }

    #pragma unroll
    for (int i = 0; i < 4; i++)
        wmma::store_matrix_sync(sh + (i * 16) * 132 + warp * 16, acc[i], 132, wmma::mem_row_major);
    __syncthreads();

    for (int idx = tid; idx < 64 * 128; idx += 256) {
        int m = idx >> 7, n = idx & 127;
        int gn = n0 + n;
        float v = sh[m * 132 + n];
        if (gn < 512) atomicAdd(&C[(size_t)m * ldc + gn], v);
        else          atomicAdd(&C2[(size_t)m * ldc2 + gn - 512], v);
    }
}

// ---------------- prologue: embedding gather + state zero -------------------
__global__ void prep_kernel(const float* __restrict__ embW,
                            const int*   __restrict__ captions)
{
    int b = blockIdx.x;           // (t, n)
    int t = b >> 6, n = b & 63;
    int e = threadIdx.x;          // 512
    int cap = captions[n * T_T + t];
    float v = embW[(size_t)cap * E_E + e];
    g_emb[((size_t)t * N_B + n) * E_E + e] = v;
    if (t == 0) {
        g_xcat[n * XDIM + ENC_C + e]       = v;     // emb slot, step 0
        g_xcat[n * XDIM + HOFF + e]        = 0.0f;  // h slot (init gemm adds)
        g_cstate[n * H_H + e]              = 0.0f;  // c (init gemm adds)
    }
}

// ---------------- prologue: concat LSTM weights (tf32-rounded) --------------
__global__ void wcat_kernel(const float* __restrict__ Wih, const float* __restrict__ bih,
                            const float* __restrict__ Whh, const float* __restrict__ bhh)
{
    int idx = blockIdx.x * 1024 + threadIdx.x;
    if (idx < GDIM * XDIM) {
        int j = idx / XDIM, k = idx % XDIM;
        float v = (k < HOFF) ? Wih[j * HOFF + k] : Whh[j * H_H + (k - HOFF)];
        g_Wcat[idx] = tf32r(v);
    }
    if (idx < GDIM) g_bcat[idx] = bih[idx] + bhh[idx];
}

// ---------------- persistent decode loop (all 32 steps, 4 phases/step) ------
__global__ void __launch_bounds__(256) decode_loop(
    const float* __restrict__ features,
    const float* __restrict__ tokW, const float* __restrict__ tokb,
    const float* __restrict__ fullW, const float* __restrict__ fullb)
{
    constexpr int SP = 68;
    __shared__ float As[64 * SP];
    __shared__ float Bs[64 * SP];
    __shared__ float s_tokW[4 * 512];   // this block's 4 attn_token_W rows
    __shared__ float s_w[A_A];
    __shared__ float s_ah[A_A];
    __shared__ float s_sc[P_P];

    const int b    = blockIdx.x;
    const int tid  = threadIdx.x;
    const int warp = tid >> 5;
    const int lane = tid & 31;

    // persistent cell state: this thread permanently owns element (en, ej)
    const int eidx = b * 256 + tid;
    const int en = eidx >> 9, ej = eidx & 511;
    float creg = g_cstate[en * H_H + ej];

    // step-invariant smem: tokW rows [4b, 4b+4) and fullW
    const int c0 = b * 4;
    #pragma unroll
    for (int i = 0; i < 2; i++) {
        int idx = tid + i * 256, c = idx >> 7, k4 = (idx & 127) << 2;
        *(float4*)(s_tokW + c * 512 + k4) =
            *(const float4*)(tokW + (size_t)(c0 + c) * H_H + k4);
    }
    for (int a = tid; a < A_A; a += 256) s_w[a] = fullW[a];
    const int pq = tid & 3;
    const float tb = tokb[c0 + pq];
    __syncthreads();

    for (int t = 0; t < T_T; t++) {
        // ===== P1: attn_h = h @ tokW^T + tokb (all 128 blocks, fp32) ========
        {
            const int n = tid >> 2;                 // 0..63
            const float* hb = g_xcat + (size_t)n * XDIM + HOFF + pq * 128;
            float a0 = 0.f, a1 = 0.f, a2 = 0.f, a3 = 0.f;
            #pragma unroll 4
            for (int j = 0; j < 128; j += 4) {
                float4 hv = __ldcg((const float4*)(hb + j));
                const float* w0 = s_tokW + pq * 128 + j;
                a0 += hv.x * w0[0]    + hv.y * w0[1]    + hv.z * w0[2]    + hv.w * w0[3];
                a1 += hv.x * w0[512]  + hv.y * w0[513]  + hv.z * w0[514]  + hv.w * w0[515];
                a2 += hv.x * w0[1024] + hv.y * w0[1025] + hv.z * w0[1026] + hv.w * w0[1027];
                a3 += hv.x * w0[1536] + hv.y * w0[1537] + hv.z * w0[1538] + hv.w * w0[1539];
            }
            #pragma unroll
            for (int off = 1; off < 4; off <<= 1) {
                a0 += __shfl_xor_sync(0xffffffffu, a0, off);
                a1 += __shfl_xor_sync(0xffffffffu, a1, off);
                a2 += __shfl_xor_sync(0xffffffffu, a2, off);
                a3 += __shfl_xor_sync(0xffffffffu, a3, off);
            }
            float r = (pq == 0) ? a0 : (pq == 1) ? a1 : (pq == 2) ? a2 : a3;
            g_attn_h[n * A_A + c0 + pq] = r + tb;
        }
        grid_sync();

        // ===== P2: attention scores + softmax + ctx (pair of blocks per n) ==
        {
            const int n = b >> 1, half = b & 1;
            for (int a = tid; a < A_A; a += 256)
                s_ah[a] = __ldcg(g_attn_h + n * A_A + a);
            __syncthreads();

            const float* aim = g_attn_img + (size_t)n * P_P * A_A;
            for (int p = warp; p < P_P; p += 8) {
                float s = 0.0f;
                const float* row = aim + p * A_A;
                #pragma unroll 4
                for (int a = lane; a < A_A; a += 32) {
                    float e = s_ah[a] + row[a];
                    if (e > 0.0f) s += e * s_w[a];
                }
                #pragma unroll
                for (int o = 16; o > 0; o >>= 1) s += __shfl_xor_sync(0xffffffffu, s, o);
                if (lane == 0) s_sc[p] = s + fullb[0];
            }
            __syncthreads();

            if (warp == 0) {
                float v0 = s_sc[lane], v1 = s_sc[lane + 32];
                float mx = fmaxf(v0, v1);
                #pragma unroll
                for (int o = 16; o > 0; o >>= 1) mx = fmaxf(mx, __shfl_xor_sync(0xffffffffu, mx, o));
                float e0 = __expf(v0 - mx), e1 = __expf(v1 - mx);
                float sm = e0 + e1;
                #pragma unroll
                for (int o = 16; o > 0; o >>= 1) sm += __shfl_xor_sync(0xffffffffu, sm, o);
                float inv = 1.0f / sm;
                s_sc[lane]      = e0 * inv;
                s_sc[lane + 32] = e1 * inv;
            }
            __syncthreads();

            const float* fn  = features + (size_t)n * P_P * ENC_C;
            float*       ctx = g_xcat + n * XDIM;
            for (int c = half * 768 + tid; c < half * 768 + 768; c += 256) {
                float a0 = 0.0f;
                #pragma unroll 8
                for (int p = 0; p < P_P; p++) a0 += s_sc[p] * fn[(size_t)p * ENC_C + c];
                ctx[c] = a0;
            }
            __syncthreads();
        }
        grid_sync();

        // ===== P3: gates split-K GEMM -> deterministic partials =============
        {
            const int nt = b >> 2, kz = b & 3;
            const int n0 = nt * 64;
            const int kb = kz * 640;
            const int m16 = (warp >> 1) * 16;
            const int nb2 = (warp & 1) * 32;
            wmma::fragment<wmma::accumulator, 16, 16, 8, float> acc[2];
            wmma::fill_fragment(acc[0], 0.0f);
            wmma::fill_fragment(acc[1], 0.0f);

            float4 ra[4], rb[4];
            #pragma unroll
            for (int i = 0; i < 4; i++) {
                int idx = tid + i * 256, m = idx >> 4, k4 = (idx & 15) << 2;
                ra[i] = __ldcg((const float4*)(g_xcat + (size_t)m * XDIM + kb + k4));
                rb[i] = *(const float4*)(g_Wcat + (size_t)(n0 + m) * XDIM + kb + k4);
            }

            for (int ko = kb; ko < kb + 640; ko += 64) {
                #pragma unroll
                for (int i = 0; i < 4; i++) {
                    int idx = tid + i * 256, m = idx >> 4, k4 = (idx & 15) << 2;
                    float* pa = As + m * SP + k4;
                    pa[0] = tf32r(ra[i].x); pa[1] = tf32r(ra[i].y);
                    pa[2] = tf32r(ra[i].z); pa[3] = tf32r(ra[i].w);
                    *(float4*)(Bs + m * SP + k4) = rb[i];   // Wcat pre-rounded
                }
                __syncthreads();

                const int kn = ko + 64;
                if (kn < kb + 640) {
                    #pragma unroll
                    for (int i = 0; i < 4; i++) {
                        int idx = tid + i * 256, m = idx >> 4, k4 = (idx & 15) << 2;
                        ra[i] = __ldcg((const float4*)(g_xcat + (size_t)m * XDIM + kn + k4));
                        rb[i] = *(const float4*)(g_Wcat + (size_t)(n0 + m) * XDIM + kn + k4);
                    }
                }

                #pragma unroll
                for (int kk = 0; kk < 64; kk += 8) {
                    wmma::fragment<wmma::matrix_a, 16, 16, 8, wmma::precision::tf32, wmma::row_major> af;
                    wmma::load_matrix_sync(af, As + m16 * SP + kk, SP);
                    #pragma unroll
                    for (int j = 0; j < 2; j++) {
                        wmma::fragment<wmma::matrix_b, 16, 16, 8, wmma::precision::tf32, wmma::col_major> bf;
                        wmma::load_matrix_sync(bf, Bs + (nb2 + j * 16) * SP + kk, SP);
                        wmma::mma_sync(acc[j], af, bf, acc[j]);
                    }
                }
                __syncthreads();
            }
            wmma::store_matrix_sync(As + m16 * SP + nb2,      acc[0], SP, wmma::mem_row_major);
            wmma::store_matrix_sync(As + m16 * SP + nb2 + 16, acc[1], SP, wmma::mem_row_major);
            __syncthreads();
            float* gp = g_gpart + (size_t)kz * (N_B * GDIM);
            for (int idx = tid; idx < 4096; idx += 256) {
                int m = idx >> 6, n = idx & 63;
                gp[m * GDIM + n0 + n] = As[m * SP + n];
            }
        }
        grid_sync();

        // ===== P4: LSTM pointwise (one element per thread, c in register) ===
        {
            float gi = g_bcat[ej];
            float gf = g_bcat[512 + ej];
            float gg = g_bcat[1024 + ej];
            float go = g_bcat[1536 + ej];
            #pragma unroll
            for (int kz = 0; kz < 4; kz++) {
                const float* g = g_gpart + (size_t)kz * (N_B * GDIM) + en * GDIM;
                gi += __ldcg(g + ej);
                gf += __ldcg(g + 512 + ej);
                gg += __ldcg(g + 1024 + ej);
                go += __ldcg(g + 1536 + ej);
            }
            float si = 1.0f / (1.0f + __expf(-gi));
            float sf = 1.0f / (1.0f + __expf(-gf));
            float so = 1.0f / (1.0f + __expf(-go));
            float cn = sf * creg + si * tanhf(gg);
            float hn = so * tanhf(cn);
            creg = cn;
            g_hall[((size_t)t * N_B + en) * H_H + ej] = hn;
            g_xcat[en * XDIM + HOFF + ej] = hn;
            if (t + 1 < T_T)
                g_xcat[en * XDIM + ENC_C + ej] = g_emb[((size_t)(t + 1) * N_B + en) * E_E + ej];
        }
        grid_sync();
    }
}

// ---------------- launch ----------------------------------------------------
extern "C" void kernel_launch(void* const* d_in, const int* in_sizes, int n_in,
                              void* d_out, int out_size)
{
    const float* features     = (const float*)d_in[0];
    const int*   captions     = (const int*)  d_in[1];
    const float* embd_W       = (const float*)d_in[2];
    const float* attn_token_W = (const float*)d_in[3];
    const float* attn_token_b = (const float*)d_in[4];
    const float* attn_feat_W  = (const float*)d_in[5];
    const float* attn_feat_b  = (const float*)d_in[6];
    const float* attn_full_W  = (const float*)d_in[7];
    const float* attn_full_b  = (const float*)d_in[8];
    const float* W_ih         = (const float*)d_in[9];
    const float* b_ih         = (const float*)d_in[10];
    const float* W_hh         = (const float*)d_in[11];
    const float* b_hh         = (const float*)d_in[12];
    const float* fc_W         = (const float*)d_in[13];
    const float* fc_b         = (const float*)d_in[14];
    const float* init_Wh      = (const float*)d_in[15];
    const float* init_Wc      = (const float*)d_in[16];
    float* out = (float*)d_out;

    float *p_attn_img, *p_xcat, *p_c, *p_hall;
    cudaGetSymbolAddress((void**)&p_attn_img, g_attn_img);
    cudaGetSymbolAddress((void**)&p_xcat,     g_xcat);
    cudaGetSymbolAddress((void**)&p_c,        g_cstate);
    cudaGetSymbolAddress((void**)&p_hall,     g_hall);

    // prologue
    prep_kernel<<<T_T * N_B, 512>>>(embd_W, captions);
    wcat_kernel<<<(GDIM * XDIM + 1023) / 1024, 1024>>>(W_ih, b_ih, W_hh, b_hh);

    // [h0 | c0] = feat_flat @ [Wh | Wc]  (merged, split-K=96, atomic)
    gemm_init<<<dim3(8, 1, 96), 256>>>(
        features, PENC, init_Wh, init_Wc, H_H,
        p_xcat + HOFF, XDIM, p_c, H_H, PENC, 1024);

    // attn_img = features @ attn_feat_W^T + b   (4096 x 512, K=1536)
    gemm_big<0><<<dim3(4, 32), 256>>>(
        features, ENC_C, attn_feat_W, ENC_C, attn_feat_b,
        p_attn_img, A_A, A_A, ENC_C);

    // full 32-step decode in one persistent kernel
    decode_loop<<<NBLK, 256>>>(features, attn_token_W, attn_token_b,
                               attn_full_W, attn_full_b);

    // preds = h_all @ fc_W^T + fc_b, remapped to (N, T, V)
    gemm_big<2><<<dim3((V_V + 127) / 128, 16), 256>>>(
        p_hall, H_H, fc_W, H_H, fc_b,
        out, V_V, V_V, H_H);
}